// round 1
// baseline (speedup 1.0000x reference)
#include <cuda_runtime.h>

typedef unsigned long long u64;

#define NBATCH 64
#define NATOM  128
#define KNB    127
#define NTYPE  4
#define D0     25
#define D0P    28
#define D1     50
#define D1P    52
#define D2     100
#define GSTR   101
#define BT     4     // batches per block

// shared memory layout (float offsets), all 16B-aligned where vector-accessed
#define OFF_W0 0            // 4*25               = 100
#define OFF_B0 100          // 4*25               = 100
#define OFF_W1 200          // 4*52*28            = 5824   [e][o][i] padded
#define OFF_B1 6024         // 4*52               = 208
#define OFF_W2 6232         // 4*100*52           = 20800  [e][m][i] padded
#define OFF_B2 27032        // 4*100              = 400
#define OFF_CS 27432        // 3*128              = 384    coords SoA [c][atom]
#define OFF_EA 27816        // 3*128              = 384    env_a SoA [c][k]
#define OFF_H0 28200        // 128*28             = 3584   per-thread h0
#define OFF_H1 31784        // 128*52             = 6656   per-thread h1
#define OFF_US 38440        // 3*100              = 300
#define OFF_G  38740        // 127*101            = 12827
#define SMEM_FLOATS 51567
#define SMEM_BYTES (SMEM_FLOATS * 4)

__device__ __forceinline__ float tanh_fast(float x) {
    // tanh(x) = 1 - 2/(e^{2x}+1); exact at +-inf saturation, ~1e-7 abs err
    float e = __expf(2.0f * x);
    return 1.0f - __fdividef(2.0f, e + 1.0f);
}
__device__ __forceinline__ u64 pack2(float lo, float hi) {
    u64 r; asm("mov.b64 %0, {%1, %2};" : "=l"(r) : "f"(lo), "f"(hi)); return r;
}
__device__ __forceinline__ float2 unpack2(u64 v) {
    float2 r; asm("mov.b64 {%0, %1}, %2;" : "=f"(r.x), "=f"(r.y) : "l"(v)); return r;
}
__device__ __forceinline__ u64 fma2(u64 a, u64 b, u64 c) {
    u64 r; asm("fma.rn.f32x2 %0, %1, %2, %3;" : "=l"(r) : "l"(a), "l"(b), "l"(c)); return r;
}
__device__ __forceinline__ u64 add2(u64 a, u64 b) {
    u64 r; asm("add.rn.f32x2 %0, %1, %2;" : "=l"(r) : "l"(a), "l"(b)); return r;
}

extern __shared__ float sm[];

__global__ void __launch_bounds__(128, 1)
feat_kernel(const float* __restrict__ coords,
            const int*   __restrict__ types,
            const float* __restrict__ W0g, const float* __restrict__ B0g,
            const float* __restrict__ W1g, const float* __restrict__ B1g,
            const float* __restrict__ W2g, const float* __restrict__ B2g,
            float* __restrict__ out)
{
    const int n   = blockIdx.x;
    const int tid = threadIdx.x;

    const int tn = types[n];
    const int eb = tn * NTYPE;

    // zero whole weight region (covers all pads; avoids NaN garbage)
    for (int i = tid; i < OFF_CS; i += 128) sm[i] = 0.0f;
    __syncthreads();

    // stage the 4 sub-type weight tables for this atom's type
    for (int i = tid; i < NTYPE * D0; i += 128) {
        sm[OFF_W0 + i] = W0g[eb * D0 + i];
        sm[OFF_B0 + i] = B0g[eb * D0 + i];
    }
    for (int idx = tid; idx < NTYPE * D1 * D0; idx += 128) {
        int i = idx % D0; int o = (idx / D0) % D1; int e = idx / (D0 * D1);
        sm[OFF_W1 + (e * D1P + o) * D0P + i] = W1g[(eb + e) * D1 * D0 + o * D0 + i];
    }
    for (int idx = tid; idx < NTYPE * D1; idx += 128) {
        int o = idx % D1; int e = idx / D1;
        sm[OFF_B1 + e * D1P + o] = B1g[(eb + e) * D1 + o];
    }
    for (int idx = tid; idx < NTYPE * D2 * D1; idx += 128) {
        int i = idx % D1; int m = (idx / D1) % D2; int e = idx / (D1 * D2);
        sm[OFF_W2 + (e * D2 + m) * D1P + i] = W2g[(eb + e) * D2 * D1 + m * D1 + i];
    }
    for (int i = tid; i < NTYPE * D2; i += 128) {
        sm[OFF_B2 + i] = B2g[eb * D2 + i];
    }

    float* h0p = sm + OFF_H0 + tid * D0P;
    float* h1p = sm + OFF_H1 + tid * D1P;
    // per-thread zero pads (stay zero forever)
    h0p[25] = 0.0f; h0p[26] = 0.0f; h0p[27] = 0.0f;
    h1p[50] = 0.0f; h1p[51] = 0.0f;

    const int j = (tid < n) ? tid : tid + 1;           // neighbor atom id
    const int e = (tid < KNB) ? types[j] : 0;          // sub-type 0..3

    const float* w1base = sm + OFF_W1 + e * D1P * D0P;
    const float* b1p    = sm + OFF_B1 + e * D1P;
    const float* w2base = sm + OFF_W2 + e * D2 * D1P;
    const float* b2p    = sm + OFF_B2 + e * D2;
    float*       grow   = sm + OFF_G  + tid * GSTR;

    for (int bi = 0; bi < BT; bi++) {
        const int b = blockIdx.y * BT + bi;
        __syncthreads();   // weights ready (bi=0) / prev iteration fully drained

        // coords of batch b -> SoA in smem
        {
            const float* cb = coords + (size_t)b * NATOM * 3;
            float cx = cb[tid * 3 + 0];
            float cy = cb[tid * 3 + 1];
            float cz = cb[tid * 3 + 2];
            sm[OFF_CS + tid]             = cx;
            sm[OFF_CS + NATOM + tid]     = cy;
            sm[OFF_CS + 2 * NATOM + tid] = cz;
        }
        __syncthreads();

        if (tid < KNB) {
            float rx = sm[OFF_CS + n]             - sm[OFF_CS + j];
            float ry = sm[OFF_CS + NATOM + n]     - sm[OFF_CS + NATOM + j];
            float rz = sm[OFF_CS + 2*NATOM + n]   - sm[OFF_CS + 2*NATOM + j];
            float d2 = rx * rx + ry * ry + rz * rz;
            float dinv = rsqrtf(d2);
            float di2 = dinv * dinv;
            sm[OFF_EA + tid]             = rx * di2;
            sm[OFF_EA + NATOM + tid]     = ry * di2;
            sm[OFF_EA + 2 * NATOM + tid] = rz * di2;
            const float x = dinv;

            // ---- layer 0: 1 -> 25 ----
            #pragma unroll
            for (int o = 0; o < D0; o++)
                h0p[o] = tanh_fast(fmaf(x, sm[OFF_W0 + e * D0 + o], sm[OFF_B0 + e * D0 + o]));

            // ---- layer 1: 25 -> 50 (+concat residual) ----
            #pragma unroll 1
            for (int o = 0; o < D1P; o += 4) {
                u64 aA0 = pack2(b1p[o+0], 0.0f), aB0 = 0ull;
                u64 aA1 = pack2(b1p[o+1], 0.0f), aB1 = 0ull;
                u64 aA2 = pack2(b1p[o+2], 0.0f), aB2 = 0ull;
                u64 aA3 = pack2(b1p[o+3], 0.0f), aB3 = 0ull;
                const float* r0 = w1base + (o+0) * D0P;
                const float* r1 = w1base + (o+1) * D0P;
                const float* r2 = w1base + (o+2) * D0P;
                const float* r3 = w1base + (o+3) * D0P;
                #pragma unroll
                for (int i = 0; i < D0P; i += 4) {
                    ulonglong2 h = *(const ulonglong2*)(h0p + i);
                    ulonglong2 w;
                    w = *(const ulonglong2*)(r0 + i); aA0 = fma2(h.x, w.x, aA0); aB0 = fma2(h.y, w.y, aB0);
                    w = *(const ulonglong2*)(r1 + i); aA1 = fma2(h.x, w.x, aA1); aB1 = fma2(h.y, w.y, aB1);
                    w = *(const ulonglong2*)(r2 + i); aA2 = fma2(h.x, w.x, aA2); aB2 = fma2(h.y, w.y, aB2);
                    w = *(const ulonglong2*)(r3 + i); aA3 = fma2(h.x, w.x, aA3); aB3 = fma2(h.y, w.y, aB3);
                }
                float2 s;
                s = unpack2(add2(aA0, aB0)); float v0 = s.x + s.y;
                s = unpack2(add2(aA1, aB1)); float v1 = s.x + s.y;
                s = unpack2(add2(aA2, aB2)); float v2 = s.x + s.y;
                s = unpack2(add2(aA3, aB3)); float v3 = s.x + s.y;
                if (o+0 < D1) h1p[o+0] = tanh_fast(v0) + h0p[(o+0) < D0 ? (o+0) : (o+0) - D0];
                if (o+1 < D1) h1p[o+1] = tanh_fast(v1) + h0p[(o+1) < D0 ? (o+1) : (o+1) - D0];
                if (o+2 < D1) h1p[o+2] = tanh_fast(v2) + h0p[(o+2) < D0 ? (o+2) : (o+2) - D0];
                if (o+3 < D1) h1p[o+3] = tanh_fast(v3) + h0p[(o+3) < D0 ? (o+3) : (o+3) - D0];
            }

            // ---- layer 2: 50 -> 100 (+concat residual), G row to smem ----
            #pragma unroll 1
            for (int m = 0; m < D2; m += 4) {
                u64 aA0 = pack2(b2p[m+0], 0.0f), aB0 = 0ull;
                u64 aA1 = pack2(b2p[m+1], 0.0f), aB1 = 0ull;
                u64 aA2 = pack2(b2p[m+2], 0.0f), aB2 = 0ull;
                u64 aA3 = pack2(b2p[m+3], 0.0f), aB3 = 0ull;
                const float* r0 = w2base + (m+0) * D1P;
                const float* r1 = w2base + (m+1) * D1P;
                const float* r2 = w2base + (m+2) * D1P;
                const float* r3 = w2base + (m+3) * D1P;
                #pragma unroll
                for (int i = 0; i < D1P; i += 4) {
                    ulonglong2 h = *(const ulonglong2*)(h1p + i);
                    ulonglong2 w;
                    w = *(const ulonglong2*)(r0 + i); aA0 = fma2(h.x, w.x, aA0); aB0 = fma2(h.y, w.y, aB0);
                    w = *(const ulonglong2*)(r1 + i); aA1 = fma2(h.x, w.x, aA1); aB1 = fma2(h.y, w.y, aB1);
                    w = *(const ulonglong2*)(r2 + i); aA2 = fma2(h.x, w.x, aA2); aB2 = fma2(h.y, w.y, aB2);
                    w = *(const ulonglong2*)(r3 + i); aA3 = fma2(h.x, w.x, aA3); aB3 = fma2(h.y, w.y, aB3);
                }
                float2 s;
                s = unpack2(add2(aA0, aB0)); float g0 = tanh_fast(s.x + s.y) + h1p[(m+0) < D1 ? (m+0) : (m+0) - D1];
                s = unpack2(add2(aA1, aB1)); float g1 = tanh_fast(s.x + s.y) + h1p[(m+1) < D1 ? (m+1) : (m+1) - D1];
                s = unpack2(add2(aA2, aB2)); float g2 = tanh_fast(s.x + s.y) + h1p[(m+2) < D1 ? (m+2) : (m+2) - D1];
                s = unpack2(add2(aA3, aB3)); float g3 = tanh_fast(s.x + s.y) + h1p[(m+3) < D1 ? (m+3) : (m+3) - D1];
                grow[m+0] = g0; grow[m+1] = g1; grow[m+2] = g2; grow[m+3] = g3;
            }
        }
        __syncthreads();

        // ---- U[c][m] = sum_k env_a[k][c] * G[k][m]  (t == U[:, :4]) ----
        float u0 = 0.0f, u1 = 0.0f, u2 = 0.0f;
        if (tid < D2) {
            #pragma unroll 1
            for (int k = 0; k < KNB; k++) {
                float g = sm[OFF_G + k * GSTR + tid];
                u0 = fmaf(sm[OFF_EA + k],             g, u0);
                u1 = fmaf(sm[OFF_EA + NATOM + k],     g, u1);
                u2 = fmaf(sm[OFF_EA + 2 * NATOM + k], g, u2);
            }
            sm[OFF_US + tid]          = u0;
            sm[OFF_US + D2 + tid]     = u1;
            sm[OFF_US + 2 * D2 + tid] = u2;
        }
        __syncthreads();

        // ---- out[m][a] = sum_c U[c][m] * U[c][a], a<4 ----
        if (tid < D2) {
            const float* Up = sm + OFF_US;
            float4 r;
            r.x = u0 * Up[0] + u1 * Up[D2 + 0] + u2 * Up[2 * D2 + 0];
            r.y = u0 * Up[1] + u1 * Up[D2 + 1] + u2 * Up[2 * D2 + 1];
            r.z = u0 * Up[2] + u1 * Up[D2 + 2] + u2 * Up[2 * D2 + 2];
            r.w = u0 * Up[3] + u1 * Up[D2 + 3] + u2 * Up[2 * D2 + 3];
            *(float4*)(out + ((size_t)b * NATOM + n) * (D2 * 4) + tid * 4) = r;
        }
    }
}

extern "C" void kernel_launch(void* const* d_in, const int* in_sizes, int n_in,
                              void* d_out, int out_size)
{
    (void)in_sizes; (void)n_in; (void)out_size;
    const float* coords = (const float*)d_in[0];
    const int*   types  = (const int*)d_in[1];
    const float* W0g = (const float*)d_in[2];
    const float* B0g = (const float*)d_in[3];
    const float* W1g = (const float*)d_in[4];
    const float* B1g = (const float*)d_in[5];
    const float* W2g = (const float*)d_in[6];
    const float* B2g = (const float*)d_in[7];
    float* out = (float*)d_out;

    cudaFuncSetAttribute(feat_kernel, cudaFuncAttributeMaxDynamicSharedMemorySize, SMEM_BYTES);

    dim3 grid(NATOM, NBATCH / BT);   // (128, 16)
    feat_kernel<<<grid, 128, SMEM_BYTES>>>(coords, types, W0g, B0g, W1g, B1g, W2g, B2g, out);
}

// round 2
// speedup vs baseline: 1.8583x; 1.8583x over previous
#include <cuda_runtime.h>

typedef unsigned long long u64;

#define NBATCH 64
#define NATOM  128
#define KNB    127
#define BT     4
#define THREADS 256

// ---- shared memory float offsets ----
#define OFF_W0 0        // [e][o25]              100
#define OFF_B0 100      // [e][o25]              100
#define OFF_W1 200      // [e][i25][o52]         4*1300
#define E1STR  1300
#define OFF_B1 5400     // [e][o52]              208
#define OFF_W2 5608     // [e][i50][m104]        4*5208
#define E2STR  5208
#define OFF_B2 26440    // [e][m104]             416
#define WEND   26856
#define OFF_CS 26856    // [3][128]              384
#define OFF_EA 27240    // [3][128]              384
#define OFF_H0 27624    // [128][27]             3456
#define OFF_H1 31080    // [128][53]             6784
#define OFF_G  37864    // [128][104]            13312
#define OFF_UP 51176    // [3][104]              312
#define OFF_US 51488    // [3][104]              312
#define SMEM_FLOATS 51800
#define SMEM_BYTES (SMEM_FLOATS * 4)

__device__ __forceinline__ float tanh_fast(float x) {
    float e = __expf(2.0f * x);
    return 1.0f - __fdividef(2.0f, e + 1.0f);
}
__device__ __forceinline__ u64 pack2(float lo, float hi) {
    u64 r; asm("mov.b64 %0, {%1, %2};" : "=l"(r) : "f"(lo), "f"(hi)); return r;
}
__device__ __forceinline__ float2 unpack2(u64 v) {
    float2 r; asm("mov.b64 {%0, %1}, %2;" : "=f"(r.x), "=f"(r.y) : "l"(v)); return r;
}
__device__ __forceinline__ u64 fma2(u64 a, u64 b, u64 c) {
    u64 r; asm("fma.rn.f32x2 %0, %1, %2, %3;" : "=l"(r) : "l"(a), "l"(b), "l"(c)); return r;
}

extern __shared__ float sm[];

// layer 1: 25 -> NT*4 outputs starting at obase; acc resident in registers
template<int NT>
__device__ __forceinline__ void layer1_tiles(const float* __restrict__ w1e,
    const float* __restrict__ b1e, const float* __restrict__ h0row,
    float* __restrict__ h1row, int obase)
{
    u64 acc[NT][2];
    #pragma unroll
    for (int t = 0; t < NT; t++) {
        float4 bb = *(const float4*)(b1e + obase + t * 4);
        acc[t][0] = pack2(bb.x, bb.y);
        acc[t][1] = pack2(bb.z, bb.w);
    }
    #pragma unroll 5
    for (int i = 0; i < 25; i++) {
        float h = h0row[i];
        u64 hd = pack2(h, h);
        const float* wp = w1e + i * 52 + obase;
        #pragma unroll
        for (int t = 0; t < NT; t++) {
            ulonglong2 w = *(const ulonglong2*)(wp + t * 4);
            acc[t][0] = fma2(w.x, hd, acc[t][0]);
            acc[t][1] = fma2(w.y, hd, acc[t][1]);
        }
    }
    #pragma unroll
    for (int t = 0; t < NT; t++) {
        int o0 = obase + t * 4;
        float2 va = unpack2(acc[t][0]);
        float2 vb = unpack2(acc[t][1]);
        h1row[o0+0] = tanh_fast(va.x) + h0row[(o0+0) < 25 ? (o0+0) : (o0+0) - 25];
        h1row[o0+1] = tanh_fast(va.y) + h0row[(o0+1) < 25 ? (o0+1) : (o0+1) - 25];
        h1row[o0+2] = tanh_fast(vb.x) + h0row[(o0+2) < 25 ? (o0+2) : (o0+2) - 25];
        h1row[o0+3] = tanh_fast(vb.y) + h0row[(o0+3) < 25 ? (o0+3) : (o0+3) - 25];
    }
}

// layer 2: 50 -> NT*8 outputs starting at mbase; acc resident in registers
template<int NT>
__device__ __forceinline__ void layer2_tiles(const float* __restrict__ w2e,
    const float* __restrict__ b2e, const float* __restrict__ h1row,
    float* __restrict__ grow, int mbase)
{
    u64 acc[NT][4];
    #pragma unroll
    for (int t = 0; t < NT; t++) {
        float4 ba = *(const float4*)(b2e + mbase + t * 8);
        float4 bb = *(const float4*)(b2e + mbase + t * 8 + 4);
        acc[t][0] = pack2(ba.x, ba.y); acc[t][1] = pack2(ba.z, ba.w);
        acc[t][2] = pack2(bb.x, bb.y); acc[t][3] = pack2(bb.z, bb.w);
    }
    #pragma unroll 2
    for (int i = 0; i < 50; i++) {
        float h = h1row[i];
        u64 hd = pack2(h, h);
        const float* wrow = w2e + i * 104 + mbase;
        #pragma unroll
        for (int t = 0; t < NT; t++) {
            ulonglong2 wa = *(const ulonglong2*)(wrow + t * 8);
            ulonglong2 wb = *(const ulonglong2*)(wrow + t * 8 + 4);
            acc[t][0] = fma2(wa.x, hd, acc[t][0]);
            acc[t][1] = fma2(wa.y, hd, acc[t][1]);
            acc[t][2] = fma2(wb.x, hd, acc[t][2]);
            acc[t][3] = fma2(wb.y, hd, acc[t][3]);
        }
    }
    #pragma unroll
    for (int t = 0; t < NT; t++) {
        int m0 = mbase + t * 8;
        float2 v0 = unpack2(acc[t][0]);
        float2 v1 = unpack2(acc[t][1]);
        float2 v2 = unpack2(acc[t][2]);
        float2 v3 = unpack2(acc[t][3]);
        float4 ga, gb;
        ga.x = tanh_fast(v0.x) + h1row[(m0+0) < 50 ? (m0+0) : (m0+0) - 50];
        ga.y = tanh_fast(v0.y) + h1row[(m0+1) < 50 ? (m0+1) : (m0+1) - 50];
        ga.z = tanh_fast(v1.x) + h1row[(m0+2) < 50 ? (m0+2) : (m0+2) - 50];
        ga.w = tanh_fast(v1.y) + h1row[(m0+3) < 50 ? (m0+3) : (m0+3) - 50];
        gb.x = tanh_fast(v2.x) + h1row[(m0+4) < 50 ? (m0+4) : (m0+4) - 50];
        gb.y = tanh_fast(v2.y) + h1row[(m0+5) < 50 ? (m0+5) : (m0+5) - 50];
        gb.z = tanh_fast(v3.x) + h1row[(m0+6) < 50 ? (m0+6) : (m0+6) - 50];
        gb.w = tanh_fast(v3.y) + h1row[(m0+7) < 50 ? (m0+7) : (m0+7) - 50];
        *(float4*)(grow + m0)     = ga;
        *(float4*)(grow + m0 + 4) = gb;
    }
}

__global__ void __launch_bounds__(THREADS, 1)
feat_kernel(const float* __restrict__ coords, const int* __restrict__ types,
            const float* __restrict__ W0g, const float* __restrict__ B0g,
            const float* __restrict__ W1g, const float* __restrict__ B1g,
            const float* __restrict__ W2g, const float* __restrict__ B2g,
            float* __restrict__ out)
{
    const int n    = blockIdx.x;
    const int tid  = threadIdx.x;
    const int k    = tid & 127;
    const int half = tid >> 7;
    const int eb   = types[n] * 4;

    // zero weight+bias region once (covers all pads)
    for (int i = tid; i < WEND; i += THREADS) sm[i] = 0.0f;
    __syncthreads();

    // stage transposed weights for this atom's 4 sub-types
    for (int i = tid; i < 100; i += THREADS) {
        sm[OFF_W0 + i] = W0g[eb * 25 + i];
        sm[OFF_B0 + i] = B0g[eb * 25 + i];
    }
    for (int idx = tid; idx < 4 * 50 * 25; idx += THREADS) {
        int i = idx % 25, o = (idx / 25) % 50, e = idx / 1250;
        sm[OFF_W1 + e * E1STR + i * 52 + o] = W1g[(eb + e) * 1250 + o * 25 + i];
    }
    for (int idx = tid; idx < 200; idx += THREADS) {
        int o = idx % 50, e = idx / 50;
        sm[OFF_B1 + e * 52 + o] = B1g[(eb + e) * 50 + o];
    }
    for (int idx = tid; idx < 4 * 100 * 50; idx += THREADS) {
        int i = idx % 50, m = (idx / 50) % 100, e = idx / 5000;
        sm[OFF_W2 + e * E2STR + i * 104 + m] = W2g[(eb + e) * 5000 + m * 50 + i];
    }
    for (int idx = tid; idx < 400; idx += THREADS) {
        int m = idx % 100, e = idx / 100;
        sm[OFF_B2 + e * 104 + m] = B2g[(eb + e) * 100 + m];
    }
    if (tid < 128) {
        sm[OFF_H0 + tid * 27 + 25] = 0.0f;   // h0 row pads (residual reads)
        sm[OFF_H0 + tid * 27 + 26] = 0.0f;
        sm[OFF_H1 + tid * 53 + 52] = 0.0f;   // h1 row pad
    }

    const int j = (k < n) ? k : k + 1;
    const int e = (k < KNB) ? types[j] : 0;
    const float* w1e = sm + OFF_W1 + e * E1STR;
    const float* b1e = sm + OFF_B1 + e * 52;
    const float* w2e = sm + OFF_W2 + e * E2STR;
    const float* b2e = sm + OFF_B2 + e * 104;
    float* h0row = sm + OFF_H0 + k * 27;
    float* h1row = sm + OFF_H1 + k * 53;
    float* grow  = sm + OFF_G  + k * 104;

    for (int bi = 0; bi < BT; bi++) {
        const int b = blockIdx.y * BT + bi;
        __syncthreads();
        // coords of batch b -> SoA
        {
            const float* cb = coords + (size_t)b * (NATOM * 3);
            for (int i = tid; i < NATOM * 3; i += THREADS)
                sm[OFF_CS + (i % 3) * NATOM + (i / 3)] = cb[i];
        }
        __syncthreads();

        // env + layer0
        if (k < KNB) {
            float rx = sm[OFF_CS + n]       - sm[OFF_CS + j];
            float ry = sm[OFF_CS + 128 + n] - sm[OFF_CS + 128 + j];
            float rz = sm[OFF_CS + 256 + n] - sm[OFF_CS + 256 + j];
            float d2 = rx * rx + ry * ry + rz * rz;
            float dinv = rsqrtf(d2);
            float di2 = dinv * dinv;
            if (!half) {
                sm[OFF_EA + k]       = rx * di2;
                sm[OFF_EA + 128 + k] = ry * di2;
                sm[OFF_EA + 256 + k] = rz * di2;
            }
            const float x = dinv;
            const int ob = half ? 13 : 0, oe = half ? 25 : 13;
            for (int o = ob; o < oe; o++)
                h0row[o] = tanh_fast(fmaf(x, sm[OFF_W0 + e * 25 + o],
                                             sm[OFF_B0 + e * 25 + o]));
        }
        __syncthreads();

        if (k < KNB) {
            if (!half) layer1_tiles<7>(w1e, b1e, h0row, h1row, 0);
            else       layer1_tiles<6>(w1e, b1e, h0row, h1row, 28);
        }
        __syncthreads();

        if (k < KNB) {
            if (!half) layer2_tiles<7>(w2e, b2e, h1row, grow, 0);
            else       layer2_tiles<6>(w2e, b2e, h1row, grow, 56);
        }
        __syncthreads();

        // U[c][m] = sum_k ea[c][k] * G[k][m]; split k over halves
        float u0 = 0.0f, u1 = 0.0f, u2 = 0.0f;
        const int m = k;
        if (m < 100) {
            const int kb = half ? 64 : 0;
            const int ke = half ? KNB : 64;
            const float* gp = sm + OFF_G + m;
            #pragma unroll 4
            for (int kk = kb; kk < ke; kk++) {
                float g = gp[kk * 104];
                u0 = fmaf(sm[OFF_EA + kk],       g, u0);
                u1 = fmaf(sm[OFF_EA + 128 + kk], g, u1);
                u2 = fmaf(sm[OFF_EA + 256 + kk], g, u2);
            }
            if (half) {
                sm[OFF_UP + m]       = u0;
                sm[OFF_UP + 104 + m] = u1;
                sm[OFF_UP + 208 + m] = u2;
            }
        }
        __syncthreads();
        if (!half && m < 100) {
            u0 += sm[OFF_UP + m];
            u1 += sm[OFF_UP + 104 + m];
            u2 += sm[OFF_UP + 208 + m];
            sm[OFF_US + m]       = u0;
            sm[OFF_US + 104 + m] = u1;
            sm[OFF_US + 208 + m] = u2;
        }
        __syncthreads();
        // out[m][a] = sum_c U[c][m]*U[c][a]
        if (!half && m < 100) {
            float4 r;
            r.x = u0 * sm[OFF_US + 0] + u1 * sm[OFF_US + 104 + 0] + u2 * sm[OFF_US + 208 + 0];
            r.y = u0 * sm[OFF_US + 1] + u1 * sm[OFF_US + 104 + 1] + u2 * sm[OFF_US + 208 + 1];
            r.z = u0 * sm[OFF_US + 2] + u1 * sm[OFF_US + 104 + 2] + u2 * sm[OFF_US + 208 + 2];
            r.w = u0 * sm[OFF_US + 3] + u1 * sm[OFF_US + 104 + 3] + u2 * sm[OFF_US + 208 + 3];
            *(float4*)(out + ((size_t)b * NATOM + n) * 400 + m * 4) = r;
        }
    }
}

extern "C" void kernel_launch(void* const* d_in, const int* in_sizes, int n_in,
                              void* d_out, int out_size)
{
    (void)in_sizes; (void)n_in; (void)out_size;
    const float* coords = (const float*)d_in[0];
    const int*   types  = (const int*)d_in[1];
    const float* W0g = (const float*)d_in[2];
    const float* B0g = (const float*)d_in[3];
    const float* W1g = (const float*)d_in[4];
    const float* B1g = (const float*)d_in[5];
    const float* W2g = (const float*)d_in[6];
    const float* B2g = (const float*)d_in[7];
    float* out = (float*)d_out;

    cudaFuncSetAttribute(feat_kernel, cudaFuncAttributeMaxDynamicSharedMemorySize, SMEM_BYTES);

    dim3 grid(NATOM, NBATCH / BT);   // (128, 16)
    feat_kernel<<<grid, THREADS, SMEM_BYTES>>>(coords, types,
                                               W0g, B0g, W1g, B1g, W2g, B2g, out);
}